// round 9
// baseline (speedup 1.0000x reference)
#include <cuda_runtime.h>
#include <math_constants.h>

#define NTOK 1024
#define DIM 128
#define TI 4            // rows per block (attn)
#define TJ 64           // j-tile
#define NT 256          // threads, attn
#define KP 132          // K/V smem pitch
#define NTILE (NTOK / TJ)
#define LOG2E 1.4426950408889634f

typedef unsigned long long ull;

// packed f32x2 helpers (sm_100+/sm_103a)
__device__ __forceinline__ ull ADD2(ull a, ull b) {
    ull r; asm("add.rn.f32x2 %0, %1, %2;" : "=l"(r) : "l"(a), "l"(b)); return r;
}
__device__ __forceinline__ ull FMA2(ull a, ull b, ull c) {
    ull r; asm("fma.rn.f32x2 %0, %1, %2, %3;" : "=l"(r) : "l"(a), "l"(b), "l"(c)); return r;
}
__device__ __forceinline__ ull RELU2(ull a) {
    float lo, hi;
    asm("mov.b64 {%0, %1}, %2;" : "=f"(lo), "=f"(hi) : "l"(a));
    lo = fmaxf(lo, 0.f); hi = fmaxf(hi, 0.f);
    ull r; asm("mov.b64 %0, {%1, %2};" : "=l"(r) : "f"(lo), "f"(hi)); return r;
}
__device__ __forceinline__ float HSUM2(ull a) {
    float lo, hi;
    asm("mov.b64 {%0, %1}, %2;" : "=f"(lo), "=f"(hi) : "l"(a));
    return lo + hi;
}

// scratch for Q,K,V (static device arrays — no allocation)
__device__ float g_Q[NTOK * DIM];
__device__ float g_K[NTOK * DIM];
__device__ float g_V[NTOK * DIM];

// ---------------------------------------------------------------------------
// Kernel 1: Q,K,V = x @ W + b.  128 blocks x 384 threads.
// ---------------------------------------------------------------------------
__global__ __launch_bounds__(384) void qkv_kernel(
    const float* __restrict__ x,
    const float* __restrict__ WQ, const float* __restrict__ bQ,
    const float* __restrict__ WK, const float* __restrict__ bK,
    const float* __restrict__ WV, const float* __restrict__ bV)
{
    __shared__ float xs[8 * DIM];
    const int tid = threadIdx.x;
    const int i0 = blockIdx.x * 8;

    for (int idx = tid; idx < 8 * DIM; idx += 384)
        xs[idx] = x[i0 * DIM + idx];
    __syncthreads();

    const int d   = tid & 127;
    const int mat = tid >> 7;   // 0=Q 1=K 2=V
    const float* W = (mat == 0) ? WQ : (mat == 1) ? WK : WV;
    const float* b = (mat == 0) ? bQ : (mat == 1) ? bK : bV;
    float* outp    = (mat == 0) ? g_Q : (mat == 1) ? g_K : g_V;

    float acc[8];
    const float bv = b[d];
#pragma unroll
    for (int r = 0; r < 8; r++) acc[r] = bv;

    for (int k = 0; k < DIM; k += 4) {
        const float w0 = W[(k + 0) * DIM + d];
        const float w1 = W[(k + 1) * DIM + d];
        const float w2 = W[(k + 2) * DIM + d];
        const float w3 = W[(k + 3) * DIM + d];
#pragma unroll
        for (int r = 0; r < 8; r++) {
            const float4 xq = *(const float4*)&xs[r * DIM + k];
            acc[r] = fmaf(xq.x, w0, fmaf(xq.y, w1, fmaf(xq.z, w2, fmaf(xq.w, w3, acc[r]))));
        }
    }
#pragma unroll
    for (int r = 0; r < 8; r++)
        outp[(i0 + r) * DIM + d] = acc[r];
}

// ---------------------------------------------------------------------------
// Kernel 2: fused pass, f32x2-packed (no softmax max-shift; |e| <~ 3).
//   phase-e: thread (je, g) computes e[4 rows] over a d-chunk with packed
//            add/fma; shfl-reduce; p = exp(e); stores DUPLICATED p8d[j][8] =
//            {p0,p0,p1,p1,p2,p2,p3,p3}; l partials in regs (lanes<8).
//   accumulate: thread owns d-PAIR (dp=tid&63) x j-quarter (jq=tid>>6);
//            packed accumulators af_r/av_r over the pair; K/V via LDS.64.
//   epilogue: exchange 4 jq partials, normalize, R@W_Ev, store.
// 256 blocks x 256 threads, smem 72.3KB -> 2 CTAs/SM.
// ---------------------------------------------------------------------------
__global__ __launch_bounds__(NT, 2) void attn_kernel(
    const float* __restrict__ wA,
    const float* __restrict__ W_Ev,
    const float* __restrict__ b_Ev,
    float* __restrict__ out)
{
    extern __shared__ float sm[];
    float* Ks   = sm;             // [TJ][KP] = 8448
    float* Vs   = sm + 8448;      // 8448
    float* Qe   = sm + 16896;     // [4][DIM] row-major = 512
    float* wAs  = sm + 17408;     // [DIM] = 128
    float* p8d  = sm + 17536;     // [TJ][8] duplicated p = 512
    float* l_ws = sm + 18048;     // [8][4] per-warp l partials = 32
    float* l_s  = sm + 18080;     // [4]
    // total 18084 floats = 72336 B

    const int tid  = threadIdx.x;
    const int lane = tid & 31;
    const int warp = tid >> 5;
    const int i0   = blockIdx.x * TI;
    // phase-e ids
    const int je   = warp * 8 + (lane & 7);   // j in [0,64)
    const int g    = lane >> 3;               // d-chunk in [0,4)
    // accumulate ids
    const int dp   = tid & 63;                // d-pair: d0=2dp, d1=2dp+1
    const int jq   = tid >> 6;                // j-quarter in [0,4)

    // init Q table (row-major) + wA
    for (int idx = tid; idx < TI * DIM; idx += NT) {
        const int r = idx >> 7, dd = idx & 127;
        Qe[idx] = g_Q[(i0 + r) * DIM + dd];   // Qe[r*DIM + dd]
    }
    if (tid < DIM) wAs[tid] = wA[tid];

    // accumulate-phase Q d-pairs in registers
    const ull q0p = *(const ull*)&g_Q[(i0 + 0) * DIM + 2 * dp];
    const ull q1p = *(const ull*)&g_Q[(i0 + 1) * DIM + 2 * dp];
    const ull q2p = *(const ull*)&g_Q[(i0 + 2) * DIM + 2 * dp];
    const ull q3p = *(const ull*)&g_Q[(i0 + 3) * DIM + 2 * dp];

    ull af0 = 0ull, af1 = 0ull, af2 = 0ull, af3 = 0ull;   // packed {d0,d1}
    ull av0 = 0ull, av1 = 0ull, av2 = 0ull, av3 = 0ull;
    float l0 = 0.f, l1 = 0.f, l2 = 0.f, l3 = 0.f;

    for (int ti = 0; ti < NTILE; ti++) {
        const float4* Kg = (const float4*)(g_K + ti * TJ * DIM);
        const float4* Vg = (const float4*)(g_V + ti * TJ * DIM);
        __syncthreads();   // A: prev accumulate done (covers Qe/wAs on ti=0)
#pragma unroll
        for (int it = 0; it < 8; it++) {
            const int idx = it * NT + tid;        // float4 index in tile
            const int j = idx >> 5, c4 = idx & 31;
            *(float4*)&Ks[j * KP + c4 * 4] = Kg[idx];
            *(float4*)&Vs[j * KP + c4 * 4] = Vg[idx];
        }
        __syncthreads();   // B: tile ready

        // ---- phase e/p (packed): e over d-chunk g for 4 rows at column je
        {
            ull e0 = 0ull, e1 = 0ull, e2 = 0ull, e3 = 0ull;
            const float* kp = Ks + je * KP;
#pragma unroll
            for (int it = 0; it < 8; it++) {
                const int b = (g + it * 4) * 4;   // float offset of 4-d block
                const ulonglong2 k2 = *(const ulonglong2*)&kp[b];
                const ulonglong2 w2 = *(const ulonglong2*)&wAs[b];
                {
                    const ulonglong2 q2 = *(const ulonglong2*)&Qe[0 * DIM + b];
                    e0 = FMA2(RELU2(ADD2(q2.x, k2.x)), w2.x, e0);
                    e0 = FMA2(RELU2(ADD2(q2.y, k2.y)), w2.y, e0);
                }
                {
                    const ulonglong2 q2 = *(const ulonglong2*)&Qe[1 * DIM + b];
                    e1 = FMA2(RELU2(ADD2(q2.x, k2.x)), w2.x, e1);
                    e1 = FMA2(RELU2(ADD2(q2.y, k2.y)), w2.y, e1);
                }
                {
                    const ulonglong2 q2 = *(const ulonglong2*)&Qe[2 * DIM + b];
                    e2 = FMA2(RELU2(ADD2(q2.x, k2.x)), w2.x, e2);
                    e2 = FMA2(RELU2(ADD2(q2.y, k2.y)), w2.y, e2);
                }
                {
                    const ulonglong2 q2 = *(const ulonglong2*)&Qe[3 * DIM + b];
                    e3 = FMA2(RELU2(ADD2(q2.x, k2.x)), w2.x, e3);
                    e3 = FMA2(RELU2(ADD2(q2.y, k2.y)), w2.y, e3);
                }
            }
            float f0 = HSUM2(e0), f1 = HSUM2(e1), f2 = HSUM2(e2), f3 = HSUM2(e3);
            // reduce partials across g (lanes l^8, l^16 share je)
#pragma unroll
            for (int off = 8; off <= 16; off <<= 1) {
                f0 += __shfl_xor_sync(0xffffffffu, f0, off);
                f1 += __shfl_xor_sync(0xffffffffu, f1, off);
                f2 += __shfl_xor_sync(0xffffffffu, f2, off);
                f3 += __shfl_xor_sync(0xffffffffu, f3, off);
            }
            // direct exp — no max subtraction (|e| <~ 3 by construction)
            const float p0 = exp2f(f0 * LOG2E);
            const float p1 = exp2f(f1 * LOG2E);
            const float p2 = exp2f(f2 * LOG2E);
            const float p3 = exp2f(f3 * LOG2E);
            if (lane < 8) {   // je = warp*8 + lane
                *(float4*)&p8d[je * 8 + 0] = make_float4(p0, p0, p1, p1);
                *(float4*)&p8d[je * 8 + 4] = make_float4(p2, p2, p3, p3);
                l0 += p0; l1 += p1; l2 += p2; l3 += p3;
            }
        }
        __syncthreads();   // C: p8d ready

        // ---- accumulate (packed): d-pair dp, rows 0..3, j-quarter jq
        {
            const float* kpb = Ks + 2 * dp;
            const float* vpb = Vs + 2 * dp;
#pragma unroll 4
            for (int jj = 0; jj < 16; jj++) {
                const int j = jq * 16 + jj;
                const ull kv = *(const ull*)&kpb[j * KP];
                const ull vv = *(const ull*)&vpb[j * KP];
                const ulonglong2 pA = *(const ulonglong2*)&p8d[j * 8];     // {p0,p0},{p1,p1}
                const ulonglong2 pB = *(const ulonglong2*)&p8d[j * 8 + 4]; // {p2,p2},{p3,p3}
                af0 = FMA2(pA.x, RELU2(ADD2(q0p, kv)), af0);
                av0 = FMA2(pA.x, vv, av0);
                af1 = FMA2(pA.y, RELU2(ADD2(q1p, kv)), af1);
                av1 = FMA2(pA.y, vv, av1);
                af2 = FMA2(pB.x, RELU2(ADD2(q2p, kv)), af2);
                av2 = FMA2(pB.x, vv, av2);
                af3 = FMA2(pB.y, RELU2(ADD2(q3p, kv)), af3);
                av3 = FMA2(pB.y, vv, av3);
            }
        }
    }

    // ================= epilogue =================
    // reduce l partials over lanes 0..7 (others hold zeros)
#pragma unroll
    for (int off = 1; off <= 4; off <<= 1) {
        l0 += __shfl_xor_sync(0xffffffffu, l0, off);
        l1 += __shfl_xor_sync(0xffffffffu, l1, off);
        l2 += __shfl_xor_sync(0xffffffffu, l2, off);
        l3 += __shfl_xor_sync(0xffffffffu, l3, off);
    }
    if (lane == 0)
        *(float4*)&l_ws[warp * 4] = make_float4(l0, l1, l2, l3);
    __syncthreads();                 // main-loop reads of Ks/Vs/p8d done

    // exchange: xch[a][jq][dp] (a: 0-3 af rows, 4-7 av rows), in Ks region
    ull* xch = (ull*)Ks;             // 8*4*64 ull = 4096 ull = 8192 floats <= 8448
    xch[(0 * 4 + jq) * 64 + dp] = af0;
    xch[(1 * 4 + jq) * 64 + dp] = af1;
    xch[(2 * 4 + jq) * 64 + dp] = af2;
    xch[(3 * 4 + jq) * 64 + dp] = af3;
    xch[(4 * 4 + jq) * 64 + dp] = av0;
    xch[(5 * 4 + jq) * 64 + dp] = av1;
    xch[(6 * 4 + jq) * 64 + dp] = av2;
    xch[(7 * 4 + jq) * 64 + dp] = av3;
    if (tid < 4) {                   // final denominator per row
        float s = 0.f;
#pragma unroll
        for (int w = 0; w < 8; w++) s += l_ws[w * 4 + tid];
        l_s[tid] = s;
    }
    __syncthreads();

    // combine over jq, normalize, publish Rp (in Vs) and avs (in Qe)
    float* Rp  = Vs;                 // [128][4] normalized R, k-major packed
    float* avs = Qe;                 // [4][128] normalized AV
    if (tid < 128) {
        const int dd = tid, dpc = tid >> 1, hc = tid & 1;
        const float* xf = (const float*)xch;
        const float4 l4 = *(const float4*)l_s;
        const float il[4] = {1.f / l4.x, 1.f / l4.y, 1.f / l4.z, 1.f / l4.w};
        float rp4[4];
#pragma unroll
        for (int r = 0; r < 4; r++) {
            float af = 0.f, av = 0.f;
#pragma unroll
            for (int q = 0; q < 4; q++) {
                af += xf[(((r    ) * 4 + q) * 64 + dpc) * 2 + hc];
                av += xf[(((4 + r) * 4 + q) * 64 + dpc) * 2 + hc];
            }
            rp4[r] = af * il[r];
            avs[r * 128 + dd] = av * il[r];
        }
        *(float4*)&Rp[dd * 4] = make_float4(rp4[0], rp4[1], rp4[2], rp4[3]);
    }
    __syncthreads();

    // GEMM: o[r][d] partial over k-range of this half
    const int d    = tid & 127;
    const int half = tid >> 7;
    float o0 = 0.f, o1 = 0.f, o2 = 0.f, o3 = 0.f;
    {
        const float* Wp = W_Ev + half * 64 * DIM + d;
#pragma unroll 4
        for (int k = 0; k < 64; k++) {
            const float wv = Wp[k * DIM];
            const float4 r4 = *(const float4*)&Rp[(half * 64 + k) * 4];  // broadcast
            o0 += r4.x * wv; o1 += r4.y * wv; o2 += r4.z * wv; o3 += r4.w * wv;
        }
    }
    __syncthreads();
    float* xg = Ks;                  // reuse as [4][128]
    if (half == 1) {
        xg[0 * 128 + d] = o0; xg[1 * 128 + d] = o1;
        xg[2 * 128 + d] = o2; xg[3 * 128 + d] = o3;
    }
    __syncthreads();
    if (half == 0) {
        const float bv = b_Ev[d];
        o0 += xg[0 * 128 + d] + avs[0 * 128 + d] + bv;
        o1 += xg[1 * 128 + d] + avs[1 * 128 + d] + bv;
        o2 += xg[2 * 128 + d] + avs[2 * 128 + d] + bv;
        o3 += xg[3 * 128 + d] + avs[3 * 128 + d] + bv;
        out[(i0 + 0) * DIM + d] = o0;
        out[(i0 + 1) * DIM + d] = o1;
        out[(i0 + 2) * DIM + d] = o2;
        out[(i0 + 3) * DIM + d] = o3;
    }
}

// ---------------------------------------------------------------------------
extern "C" void kernel_launch(void* const* d_in, const int* in_sizes, int n_in,
                              void* d_out, int out_size)
{
    const float* x    = (const float*)d_in[0];
    const float* W_Q  = (const float*)d_in[1];
    const float* b_Q  = (const float*)d_in[2];
    const float* W_K  = (const float*)d_in[3];
    const float* b_K  = (const float*)d_in[4];
    const float* W_V  = (const float*)d_in[5];
    const float* b_V  = (const float*)d_in[6];
    const float* W_Ev = (const float*)d_in[7];
    const float* b_Ev = (const float*)d_in[8];
    const float* W_A  = (const float*)d_in[9];
    // d_in[10] = b_A: cancels in softmax; sum(alpha)=1 handles b_Ev; unused.
    float* out = (float*)d_out;

    const int smem2 = 18084 * (int)sizeof(float);  // 72336 B -> 2 CTAs/SM
    cudaFuncSetAttribute(attn_kernel, cudaFuncAttributeMaxDynamicSharedMemorySize, smem2);

    qkv_kernel<<<NTOK / 8, 384>>>(x, W_Q, b_Q, W_K, b_K, W_V, b_V);
    attn_kernel<<<NTOK / TI, NT, smem2>>>(W_A, W_Ev, b_Ev, out);
}

// round 10
// speedup vs baseline: 1.0208x; 1.0208x over previous
#include <cuda_runtime.h>
#include <math_constants.h>

#define NTOK 1024
#define DIM 128
#define TI 4            // rows per block (attn)
#define TJ 64           // j-tile
#define NT 256          // threads, attn
#define KP 132          // K/V smem pitch
#define NTILE (NTOK / TJ)
#define LOG2E 1.4426950408889634f

typedef unsigned long long ull;

// packed f32x2 helpers (sm_100+/sm_103a)
__device__ __forceinline__ ull ADD2(ull a, ull b) {
    ull r; asm("add.rn.f32x2 %0, %1, %2;" : "=l"(r) : "l"(a), "l"(b)); return r;
}
__device__ __forceinline__ ull FMA2(ull a, ull b, ull c) {
    ull r; asm("fma.rn.f32x2 %0, %1, %2, %3;" : "=l"(r) : "l"(a), "l"(b), "l"(c)); return r;
}
__device__ __forceinline__ ull RELU2(ull a) {
    float lo, hi;
    asm("mov.b64 {%0, %1}, %2;" : "=f"(lo), "=f"(hi) : "l"(a));
    lo = fmaxf(lo, 0.f); hi = fmaxf(hi, 0.f);
    ull r; asm("mov.b64 %0, {%1, %2};" : "=l"(r) : "f"(lo), "f"(hi)); return r;
}
__device__ __forceinline__ float HSUM2(ull a) {
    float lo, hi;
    asm("mov.b64 {%0, %1}, %2;" : "=f"(lo), "=f"(hi) : "l"(a));
    return lo + hi;
}
// cp.async 16B, L2-bypass-L1 variant
__device__ __forceinline__ void cpa16(unsigned dst, const void* src) {
    asm volatile("cp.async.cg.shared.global [%0], [%1], 16;" :: "r"(dst), "l"(src));
}
#define CP_COMMIT() asm volatile("cp.async.commit_group;" ::: "memory")
#define CP_WAIT0()  asm volatile("cp.async.wait_group 0;" ::: "memory")

// scratch for Q,K,V (static device arrays — no allocation)
__device__ float g_Q[NTOK * DIM];
__device__ float g_K[NTOK * DIM];
__device__ float g_V[NTOK * DIM];

// ---------------------------------------------------------------------------
// Kernel 1: Q,K,V = x @ W + b.  128 blocks x 384 threads.
// ---------------------------------------------------------------------------
__global__ __launch_bounds__(384) void qkv_kernel(
    const float* __restrict__ x,
    const float* __restrict__ WQ, const float* __restrict__ bQ,
    const float* __restrict__ WK, const float* __restrict__ bK,
    const float* __restrict__ WV, const float* __restrict__ bV)
{
    __shared__ float xs[8 * DIM];
    const int tid = threadIdx.x;
    const int i0 = blockIdx.x * 8;

    for (int idx = tid; idx < 8 * DIM; idx += 384)
        xs[idx] = x[i0 * DIM + idx];
    __syncthreads();

    const int d   = tid & 127;
    const int mat = tid >> 7;   // 0=Q 1=K 2=V
    const float* W = (mat == 0) ? WQ : (mat == 1) ? WK : WV;
    const float* b = (mat == 0) ? bQ : (mat == 1) ? bK : bV;
    float* outp    = (mat == 0) ? g_Q : (mat == 1) ? g_K : g_V;

    float acc[8];
    const float bv = b[d];
#pragma unroll
    for (int r = 0; r < 8; r++) acc[r] = bv;

    for (int k = 0; k < DIM; k += 4) {
        const float w0 = W[(k + 0) * DIM + d];
        const float w1 = W[(k + 1) * DIM + d];
        const float w2 = W[(k + 2) * DIM + d];
        const float w3 = W[(k + 3) * DIM + d];
#pragma unroll
        for (int r = 0; r < 8; r++) {
            const float4 xq = *(const float4*)&xs[r * DIM + k];
            acc[r] = fmaf(xq.x, w0, fmaf(xq.y, w1, fmaf(xq.z, w2, fmaf(xq.w, w3, acc[r]))));
        }
    }
#pragma unroll
    for (int r = 0; r < 8; r++)
        outp[(i0 + r) * DIM + d] = acc[r];
}

// ---------------------------------------------------------------------------
// Kernel 2: fused pass, f32x2-packed, cp.async pipelined.
//   K double-buffered (read by BOTH phases), V single-buffered.
//   Per tile: [wait K(ti)+sync] issue V(ti); phase-e; [wait V+sync] issue
//   K(ti+1); accumulate.  2 barriers/tile, loads overlap compute.
// 256 blocks x 256 threads, smem ~106KB -> 2 CTAs/SM.
// ---------------------------------------------------------------------------
__global__ __launch_bounds__(NT, 2) void attn_kernel(
    const float* __restrict__ wA,
    const float* __restrict__ W_Ev,
    const float* __restrict__ b_Ev,
    float* __restrict__ out)
{
    extern __shared__ float sm[];
    float* Ks0  = sm;             // [TJ][KP] = 8448
    float* Ks1  = sm + 8448;      // 8448
    float* Vs   = sm + 16896;     // 8448
    float* Qe   = sm + 25344;     // [4][DIM] = 512
    float* wAs  = sm + 25856;     // [DIM] = 128
    float* p8d  = sm + 25984;     // [TJ][8] duplicated p = 512
    float* l_ws = sm + 26496;     // [8][4] = 32
    float* l_s  = sm + 26528;     // [4]
    // total 26532 floats = 106128 B

    const int tid  = threadIdx.x;
    const int lane = tid & 31;
    const int warp = tid >> 5;
    const int i0   = blockIdx.x * TI;
    // phase-e ids
    const int je   = warp * 8 + (lane & 7);   // j in [0,64)
    const int g    = lane >> 3;               // d-chunk in [0,4)
    // accumulate ids
    const int dp   = tid & 63;                // d-pair: d0=2dp, d1=2dp+1
    const int jq   = tid >> 6;                // j-quarter in [0,4)

    // this thread's tile slot (same for every tile): float4 idx = it*NT+tid
    // j = idx>>5, c4 = idx&31  ->  smem offset j*KP + c4*4 floats
    unsigned koff[8], base0, base1, vbase;
    {
        base0 = (unsigned)__cvta_generic_to_shared(Ks0);
        base1 = (unsigned)__cvta_generic_to_shared(Ks1);
        vbase = (unsigned)__cvta_generic_to_shared(Vs);
#pragma unroll
        for (int it = 0; it < 8; it++) {
            const int idx = it * NT + tid;
            koff[it] = (unsigned)(((idx >> 5) * KP + (idx & 31) * 4) * 4);
        }
    }

    // init Q table (row-major) + wA
    for (int idx = tid; idx < TI * DIM; idx += NT) {
        const int r = idx >> 7, dd = idx & 127;
        Qe[idx] = g_Q[(i0 + r) * DIM + dd];   // Qe[r*DIM + dd]
    }
    if (tid < DIM) wAs[tid] = wA[tid];

    // accumulate-phase Q d-pairs in registers
    const ull q0p = *(const ull*)&g_Q[(i0 + 0) * DIM + 2 * dp];
    const ull q1p = *(const ull*)&g_Q[(i0 + 1) * DIM + 2 * dp];
    const ull q2p = *(const ull*)&g_Q[(i0 + 2) * DIM + 2 * dp];
    const ull q3p = *(const ull*)&g_Q[(i0 + 3) * DIM + 2 * dp];

    ull af0 = 0ull, af1 = 0ull, af2 = 0ull, af3 = 0ull;   // packed {d0,d1}
    ull av0 = 0ull, av1 = 0ull, av2 = 0ull, av3 = 0ull;
    float l0 = 0.f, l1 = 0.f, l2 = 0.f, l3 = 0.f;

    // prologue: async-load K(0) into Ks0
    {
        const float4* Kg = (const float4*)(g_K + 0 * TJ * DIM);
#pragma unroll
        for (int it = 0; it < 8; it++)
            cpa16(base0 + koff[it], &Kg[it * NT + tid]);
        CP_COMMIT();
    }

    for (int ti = 0; ti < NTILE; ti++) {
        const unsigned kb = (ti & 1) ? base1 : base0;
        const float* Kcur = (ti & 1) ? Ks1 : Ks0;

        CP_WAIT0();        // K(ti) landed
        __syncthreads();   // visible to all; prev accumulate done (Vs, p8d, K other buf free)

        // issue V(ti) — overlaps phase-e
        {
            const float4* Vg = (const float4*)(g_V + ti * TJ * DIM);
#pragma unroll
            for (int it = 0; it < 8; it++)
                cpa16(vbase + koff[it], &Vg[it * NT + tid]);
            CP_COMMIT();
        }

        // ---- phase e/p (packed): e over d-chunk g for 4 rows at column je
        {
            ull e0 = 0ull, e1 = 0ull, e2 = 0ull, e3 = 0ull;
            const float* kp = Kcur + je * KP;
#pragma unroll
            for (int it = 0; it < 8; it++) {
                const int b = (g + it * 4) * 4;   // float offset of 4-d block
                const ulonglong2 k2 = *(const ulonglong2*)&kp[b];
                const ulonglong2 w2 = *(const ulonglong2*)&wAs[b];
                {
                    const ulonglong2 q2 = *(const ulonglong2*)&Qe[0 * DIM + b];
                    e0 = FMA2(RELU2(ADD2(q2.x, k2.x)), w2.x, e0);
                    e0 = FMA2(RELU2(ADD2(q2.y, k2.y)), w2.y, e0);
                }
                {
                    const ulonglong2 q2 = *(const ulonglong2*)&Qe[1 * DIM + b];
                    e1 = FMA2(RELU2(ADD2(q2.x, k2.x)), w2.x, e1);
                    e1 = FMA2(RELU2(ADD2(q2.y, k2.y)), w2.y, e1);
                }
                {
                    const ulonglong2 q2 = *(const ulonglong2*)&Qe[2 * DIM + b];
                    e2 = FMA2(RELU2(ADD2(q2.x, k2.x)), w2.x, e2);
                    e2 = FMA2(RELU2(ADD2(q2.y, k2.y)), w2.y, e2);
                }
                {
                    const ulonglong2 q2 = *(const ulonglong2*)&Qe[3 * DIM + b];
                    e3 = FMA2(RELU2(ADD2(q2.x, k2.x)), w2.x, e3);
                    e3 = FMA2(RELU2(ADD2(q2.y, k2.y)), w2.y, e3);
                }
            }
            float f0 = HSUM2(e0), f1 = HSUM2(e1), f2 = HSUM2(e2), f3 = HSUM2(e3);
            // reduce partials across g (lanes l^8, l^16 share je)
#pragma unroll
            for (int off = 8; off <= 16; off <<= 1) {
                f0 += __shfl_xor_sync(0xffffffffu, f0, off);
                f1 += __shfl_xor_sync(0xffffffffu, f1, off);
                f2 += __shfl_xor_sync(0xffffffffu, f2, off);
                f3 += __shfl_xor_sync(0xffffffffu, f3, off);
            }
            // direct exp — no max subtraction (|e| <~ 3 by construction)
            const float p0 = exp2f(f0 * LOG2E);
            const float p1 = exp2f(f1 * LOG2E);
            const float p2 = exp2f(f2 * LOG2E);
            const float p3 = exp2f(f3 * LOG2E);
            if (lane < 8) {   // je = warp*8 + lane
                *(float4*)&p8d[je * 8 + 0] = make_float4(p0, p0, p1, p1);
                *(float4*)&p8d[je * 8 + 4] = make_float4(p2, p2, p3, p3);
                l0 += p0; l1 += p1; l2 += p2; l3 += p3;
            }
        }

        CP_WAIT0();        // V(ti) landed (only outstanding group)
        __syncthreads();   // p8d + V visible

        // issue K(ti+1) into other buffer — overlaps accumulate
        if (ti + 1 < NTILE) {
            const unsigned kb2 = (ti & 1) ? base0 : base1;
            const float4* Kg = (const float4*)(g_K + (ti + 1) * TJ * DIM);
#pragma unroll
            for (int it = 0; it < 8; it++)
                cpa16(kb2 + koff[it], &Kg[it * NT + tid]);
            CP_COMMIT();
        }

        // ---- accumulate (packed): d-pair dp, rows 0..3, j-quarter jq
        {
            const float* kpb = Kcur + 2 * dp;
            const float* vpb = Vs + 2 * dp;
#pragma unroll 4
            for (int jj = 0; jj < 16; jj++) {
                const int j = jq * 16 + jj;
                const ull kv = *(const ull*)&kpb[j * KP];
                const ull vv = *(const ull*)&vpb[j * KP];
                const ulonglong2 pA = *(const ulonglong2*)&p8d[j * 8];     // {p0,p0},{p1,p1}
                const ulonglong2 pB = *(const ulonglong2*)&p8d[j * 8 + 4]; // {p2,p2},{p3,p3}
                af0 = FMA2(pA.x, RELU2(ADD2(q0p, kv)), af0);
                av0 = FMA2(pA.x, vv, av0);
                af1 = FMA2(pA.y, RELU2(ADD2(q1p, kv)), af1);
                av1 = FMA2(pA.y, vv, av1);
                af2 = FMA2(pB.x, RELU2(ADD2(q2p, kv)), af2);
                av2 = FMA2(pB.x, vv, av2);
                af3 = FMA2(pB.y, RELU2(ADD2(q3p, kv)), af3);
                av3 = FMA2(pB.y, vv, av3);
            }
        }
    }

    // ================= epilogue =================
    // reduce l partials over lanes 0..7 (others hold zeros)
#pragma unroll
    for (int off = 1; off <= 4; off <<= 1) {
        l0 += __shfl_xor_sync(0xffffffffu, l0, off);
        l1 += __shfl_xor_sync(0xffffffffu, l1, off);
        l2 += __shfl_xor_sync(0xffffffffu, l2, off);
        l3 += __shfl_xor_sync(0xffffffffu, l3, off);
    }
    if (lane == 0)
        *(float4*)&l_ws[warp * 4] = make_float4(l0, l1, l2, l3);
    CP_WAIT0();                      // drain any outstanding group
    __syncthreads();                 // main-loop reads done

    // exchange: xch[a][jq][dp] (a: 0-3 af rows, 4-7 av rows), in Ks0 region
    ull* xch = (ull*)Ks0;            // 8*4*64 ull = 4096 ull = 8192 floats <= 8448
    xch[(0 * 4 + jq) * 64 + dp] = af0;
    xch[(1 * 4 + jq) * 64 + dp] = af1;
    xch[(2 * 4 + jq) * 64 + dp] = af2;
    xch[(3 * 4 + jq) * 64 + dp] = af3;
    xch[(4 * 4 + jq) * 64 + dp] = av0;
    xch[(5 * 4 + jq) * 64 + dp] = av1;
    xch[(6 * 4 + jq) * 64 + dp] = av2;
    xch[(7 * 4 + jq) * 64 + dp] = av3;
    if (tid < 4) {                   // final denominator per row
        float s = 0.f;
#pragma unroll
        for (int w = 0; w < 8; w++) s += l_ws[w * 4 + tid];
        l_s[tid] = s;
    }
    __syncthreads();

    // combine over jq, normalize, publish Rp (in Vs) and avs (in Qe)
    float* Rp  = Vs;                 // [128][4] normalized R, k-major packed
    float* avs = Qe;                 // [4][128] normalized AV
    if (tid < 128) {
        const int dd = tid, dpc = tid >> 1, hc = tid & 1;
        const float* xf = (const float*)xch;
        const float4 l4 = *(const float4*)l_s;
        const float il[4] = {1.f / l4.x, 1.f / l4.y, 1.f / l4.z, 1.f / l4.w};
        float rp4[4];
#pragma unroll
        for (int r = 0; r < 4; r++) {
            float af = 0.f, av = 0.f;
#pragma unroll
            for (int q = 0; q < 4; q++) {
                af += xf[(((r    ) * 4 + q) * 64 + dpc) * 2 + hc];
                av += xf[(((4 + r) * 4 + q) * 64 + dpc) * 2 + hc];
            }
            rp4[r] = af * il[r];
            avs[r * 128 + dd] = av * il[r];
        }
        *(float4*)&Rp[dd * 4] = make_float4(rp4[0], rp4[1], rp4[2], rp4[3]);
    }
    __syncthreads();

    // GEMM: o[r][d] partial over k-range of this half
    const int d    = tid & 127;
    const int half = tid >> 7;
    float o0 = 0.f, o1 = 0.f, o2 = 0.f, o3 = 0.f;
    {
        const float* Wp = W_Ev + half * 64 * DIM + d;
#pragma unroll 4
        for (int k = 0; k < 64; k++) {
            const float wv = Wp[k * DIM];
            const float4 r4 = *(const float4*)&Rp[(half * 64 + k) * 4];  // broadcast
            o0 += r4.x * wv; o1 += r4.y * wv; o2 += r4.z * wv; o3 += r4.w * wv;
        }
    }
    __syncthreads();
    float* xg = Ks0;                 // reuse as [4][128]
    if (half == 1) {
        xg[0 * 128 + d] = o0; xg[1 * 128 + d] = o1;
        xg[2 * 128 + d] = o2; xg[3 * 128 + d] = o3;
    }
    __syncthreads();
    if (half == 0) {
        const float bv = b_Ev[d];
        o0 += xg[0 * 128 + d] + avs[0 * 128 + d] + bv;
        o1 += xg[1 * 128 + d] + avs[1 * 128 + d] + bv;
        o2 += xg[2 * 128 + d] + avs[2 * 128 + d] + bv;
        o3 += xg[3 * 128 + d] + avs[3 * 128 + d] + bv;
        out[(i0 + 0) * DIM + d] = o0;
        out[(i0 + 1) * DIM + d] = o1;
        out[(i0 + 2) * DIM + d] = o2;
        out[(i0 + 3) * DIM + d] = o3;
    }
}

// ---------------------------------------------------------------------------
extern "C" void kernel_launch(void* const* d_in, const int* in_sizes, int n_in,
                              void* d_out, int out_size)
{
    const float* x    = (const float*)d_in[0];
    const float* W_Q  = (const float*)d_in[1];
    const float* b_Q  = (const float*)d_in[2];
    const float* W_K  = (const float*)d_in[3];
    const float* b_K  = (const float*)d_in[4];
    const float* W_V  = (const float*)d_in[5];
    const float* b_V  = (const float*)d_in[6];
    const float* W_Ev = (const float*)d_in[7];
    const float* b_Ev = (const float*)d_in[8];
    const float* W_A  = (const float*)d_in[9];
    // d_in[10] = b_A: cancels in softmax; sum(alpha)=1 handles b_Ev; unused.
    float* out = (float*)d_out;

    const int smem2 = 26532 * (int)sizeof(float);  // 106128 B -> 2 CTAs/SM
    cudaFuncSetAttribute(attn_kernel, cudaFuncAttributeMaxDynamicSharedMemorySize, smem2);

    qkv_kernel<<<NTOK / 8, 384>>>(x, W_Q, b_Q, W_K, b_K, W_V, b_V);
    attn_kernel<<<NTOK / TI, NT, smem2>>>(W_A, W_Ev, b_Ev, out);
}

// round 12
// speedup vs baseline: 1.0443x; 1.0230x over previous
#include <cuda_runtime.h>
#include <math_constants.h>

#define NTOK 1024
#define DIM 128
#define TI 4            // rows per block (attn)
#define TJ 64           // j-tile
#define NT 256          // threads, attn
#define KP 132          // K/V smem pitch
#define NTILE (NTOK / TJ)
#define LOG2E 1.4426950408889634f

typedef unsigned long long ull;

// packed f32x2 helpers (sm_100+/sm_103a)
__device__ __forceinline__ ull ADD2(ull a, ull b) {
    ull r; asm("add.rn.f32x2 %0, %1, %2;" : "=l"(r) : "l"(a), "l"(b)); return r;
}
__device__ __forceinline__ ull FMA2(ull a, ull b, ull c) {
    ull r; asm("fma.rn.f32x2 %0, %1, %2, %3;" : "=l"(r) : "l"(a), "l"(b), "l"(c)); return r;
}
// packed relu via scalar FMNMX pair (no packed f32 max exists; FMNMX = alu pipe)
__device__ __forceinline__ ull RELU2(ull a) {
    float lo, hi;
    asm("mov.b64 {%0, %1}, %2;" : "=f"(lo), "=f"(hi) : "l"(a));
    lo = fmaxf(lo, 0.f); hi = fmaxf(hi, 0.f);
    ull r; asm("mov.b64 %0, {%1, %2};" : "=l"(r) : "f"(lo), "f"(hi)); return r;
}
__device__ __forceinline__ float HSUM2(ull a) {
    float lo, hi;
    asm("mov.b64 {%0, %1}, %2;" : "=f"(lo), "=f"(hi) : "l"(a));
    return lo + hi;
}
// cp.async 16B, L2-bypass-L1 variant
__device__ __forceinline__ void cpa16(unsigned dst, const void* src) {
    asm volatile("cp.async.cg.shared.global [%0], [%1], 16;" :: "r"(dst), "l"(src));
}
#define CP_COMMIT() asm volatile("cp.async.commit_group;" ::: "memory")
#define CP_WAIT0()  asm volatile("cp.async.wait_group 0;" ::: "memory")

// scratch for Q,K,V (static device arrays — no allocation)
__device__ float g_Q[NTOK * DIM];
__device__ float g_K[NTOK * DIM];
__device__ float g_V[NTOK * DIM];

// ---------------------------------------------------------------------------
// Kernel 1: Q,K,V = x @ W + b.  128 blocks x 384 threads.
// ---------------------------------------------------------------------------
__global__ __launch_bounds__(384) void qkv_kernel(
    const float* __restrict__ x,
    const float* __restrict__ WQ, const float* __restrict__ bQ,
    const float* __restrict__ WK, const float* __restrict__ bK,
    const float* __restrict__ WV, const float* __restrict__ bV)
{
    __shared__ float xs[8 * DIM];
    const int tid = threadIdx.x;
    const int i0 = blockIdx.x * 8;

    for (int idx = tid; idx < 8 * DIM; idx += 384)
        xs[idx] = x[i0 * DIM + idx];
    __syncthreads();

    const int d   = tid & 127;
    const int mat = tid >> 7;   // 0=Q 1=K 2=V
    const float* W = (mat == 0) ? WQ : (mat == 1) ? WK : WV;
    const float* b = (mat == 0) ? bQ : (mat == 1) ? bK : bV;
    float* outp    = (mat == 0) ? g_Q : (mat == 1) ? g_K : g_V;

    float acc[8];
    const float bv = b[d];
#pragma unroll
    for (int r = 0; r < 8; r++) acc[r] = bv;

#pragma unroll 4
    for (int k = 0; k < DIM; k += 4) {
        const float w0 = W[(k + 0) * DIM + d];
        const float w1 = W[(k + 1) * DIM + d];
        const float w2 = W[(k + 2) * DIM + d];
        const float w3 = W[(k + 3) * DIM + d];
#pragma unroll
        for (int r = 0; r < 8; r++) {
            const float4 xq = *(const float4*)&xs[r * DIM + k];
            acc[r] = fmaf(xq.x, w0, fmaf(xq.y, w1, fmaf(xq.z, w2, fmaf(xq.w, w3, acc[r]))));
        }
    }
#pragma unroll
    for (int r = 0; r < 8; r++)
        outp[(i0 + r) * DIM + d] = acc[r];
}

// ---------------------------------------------------------------------------
// Kernel 2: fused pass, f32x2-packed, cp.async pipelined.
//   K double-buffered, V single-buffered. 2 barriers/tile.
//   Phase-e uses a 3-shfl reduce-scatter so each thread owns ONE (row g, je)
//   logit -> 1 exp2/thread, 1 l register/thread.
// 256 blocks x 256 threads, smem ~106KB -> 2 CTAs/SM.
// ---------------------------------------------------------------------------
__global__ __launch_bounds__(NT, 2) void attn_kernel(
    const float* __restrict__ wA,
    const float* __restrict__ W_Ev,
    const float* __restrict__ b_Ev,
    float* __restrict__ out)
{
    extern __shared__ float sm[];
    float* Ks0  = sm;             // [TJ][KP] = 8448
    float* Ks1  = sm + 8448;      // 8448
    float* Vs   = sm + 16896;     // 8448
    float* Qe   = sm + 25344;     // [4][DIM] = 512
    float* wAs  = sm + 25856;     // [DIM] = 128
    float* p8d  = sm + 25984;     // [TJ][8] duplicated p = 512
    float* l_ws = sm + 26496;     // [8][4] = 32
    float* l_s  = sm + 26528;     // [4]
    // total 26532 floats = 106128 B

    const int tid  = threadIdx.x;
    const int lane = tid & 31;
    const int warp = tid >> 5;
    const int i0   = blockIdx.x * TI;
    // phase-e ids
    const int je   = warp * 8 + (lane & 7);   // j in [0,64)
    const int g    = lane >> 3;               // d-chunk / owned row in [0,4)
    // accumulate ids
    const int dp   = tid & 63;                // d-pair: d0=2dp, d1=2dp+1
    const int jq   = tid >> 6;                // j-quarter in [0,4)

    // this thread's tile slot (same for every tile): float4 idx = it*NT+tid
    unsigned koff[8], base0, base1, vbase;
    {
        base0 = (unsigned)__cvta_generic_to_shared(Ks0);
        base1 = (unsigned)__cvta_generic_to_shared(Ks1);
        vbase = (unsigned)__cvta_generic_to_shared(Vs);
#pragma unroll
        for (int it = 0; it < 8; it++) {
            const int idx = it * NT + tid;
            koff[it] = (unsigned)(((idx >> 5) * KP + (idx & 31) * 4) * 4);
        }
    }

    // init Q table (row-major) + wA
    for (int idx = tid; idx < TI * DIM; idx += NT) {
        const int r = idx >> 7, dd = idx & 127;
        Qe[idx] = g_Q[(i0 + r) * DIM + dd];   // Qe[r*DIM + dd]
    }
    if (tid < DIM) wAs[tid] = wA[tid];

    // accumulate-phase Q d-pairs in registers
    const ull q0p = *(const ull*)&g_Q[(i0 + 0) * DIM + 2 * dp];
    const ull q1p = *(const ull*)&g_Q[(i0 + 1) * DIM + 2 * dp];
    const ull q2p = *(const ull*)&g_Q[(i0 + 2) * DIM + 2 * dp];
    const ull q3p = *(const ull*)&g_Q[(i0 + 3) * DIM + 2 * dp];

    ull af0 = 0ull, af1 = 0ull, af2 = 0ull, af3 = 0ull;   // packed {d0,d1}
    ull av0 = 0ull, av1 = 0ull, av2 = 0ull, av3 = 0ull;
    float l_acc = 0.f;            // denominator partial for row g at cols je

    // prologue: async-load K(0) into Ks0
    {
        const float4* Kg = (const float4*)(g_K + 0 * TJ * DIM);
#pragma unroll
        for (int it = 0; it < 8; it++)
            cpa16(base0 + koff[it], &Kg[it * NT + tid]);
        CP_COMMIT();
    }

    for (int ti = 0; ti < NTILE; ti++) {
        const float* Kcur = (ti & 1) ? Ks1 : Ks0;

        CP_WAIT0();        // K(ti) landed
        __syncthreads();   // visible to all; prev accumulate done

        // issue V(ti) — overlaps phase-e
        {
            const float4* Vg = (const float4*)(g_V + ti * TJ * DIM);
#pragma unroll
            for (int it = 0; it < 8; it++)
                cpa16(vbase + koff[it], &Vg[it * NT + tid]);
            CP_COMMIT();
        }

        // ---- phase e/p (packed): e over d-chunk g for 4 rows at column je
        {
            ull e0 = 0ull, e1 = 0ull, e2 = 0ull, e3 = 0ull;
            const float* kp = Kcur + je * KP;
#pragma unroll
            for (int it = 0; it < 8; it++) {
                const int b = (g + it * 4) * 4;   // float offset of 4-d block
                const ulonglong2 k2 = *(const ulonglong2*)&kp[b];
                const ulonglong2 w2 = *(const ulonglong2*)&wAs[b];
                {
                    const ulonglong2 q2 = *(const ulonglong2*)&Qe[0 * DIM + b];
                    e0 = FMA2(RELU2(ADD2(q2.x, k2.x)), w2.x, e0);
                    e0 = FMA2(RELU2(ADD2(q2.y, k2.y)), w2.y, e0);
                }
                {
                    const ulonglong2 q2 = *(const ulonglong2*)&Qe[1 * DIM + b];
                    e1 = FMA2(RELU2(ADD2(q2.x, k2.x)), w2.x, e1);
                    e1 = FMA2(RELU2(ADD2(q2.y, k2.y)), w2.y, e1);
                }
                {
                    const ulonglong2 q2 = *(const ulonglong2*)&Qe[2 * DIM + b];
                    e2 = FMA2(RELU2(ADD2(q2.x, k2.x)), w2.x, e2);
                    e2 = FMA2(RELU2(ADD2(q2.y, k2.y)), w2.y, e2);
                }
                {
                    const ulonglong2 q2 = *(const ulonglong2*)&Qe[3 * DIM + b];
                    e3 = FMA2(RELU2(ADD2(q2.x, k2.x)), w2.x, e3);
                    e3 = FMA2(RELU2(ADD2(q2.y, k2.y)), w2.y, e3);
                }
            }
            float f0 = HSUM2(e0), f1 = HSUM2(e1), f2 = HSUM2(e2), f3 = HSUM2(e3);
            // reduce-scatter over g (3 shfls): thread ends with row g's full e
            const bool hi0 = (g & 1);
            float sA = hi0 ? f0 : f1;
            float sB = hi0 ? f2 : f3;
            const float rA = __shfl_xor_sync(0xffffffffu, sA, 8);
            const float rB = __shfl_xor_sync(0xffffffffu, sB, 8);
            const float u = (hi0 ? f1 : f0) + rA;   // row (g&1)
            const float v = (hi0 ? f3 : f2) + rB;   // row 2+(g&1)
            const bool hi1 = (g >> 1);
            float s2 = hi1 ? u : v;
            const float r2 = __shfl_xor_sync(0xffffffffu, s2, 16);
            const float e = (hi1 ? v : u) + r2;     // row g, column je
            // direct exp — no max subtraction (|e| <~ 3 by construction)
            const float p = exp2f(e * LOG2E);
            *(float2*)&p8d[je * 8 + 2 * g] = make_float2(p, p);
            l_acc += p;
        }

        CP_WAIT0();        // V(ti) landed (only outstanding group)
        __syncthreads();   // p8d + V visible

        // issue K(ti+1) into other buffer — overlaps accumulate
        if (ti + 1 < NTILE) {
            const unsigned kb2 = (ti & 1) ? base0 : base1;
            const float4* Kg = (const float4*)(g_K + (ti + 1) * TJ * DIM);
#pragma unroll
            for (int it = 0; it < 8; it++)
                cpa16(kb2 + koff[it], &Kg[it * NT + tid]);
            CP_COMMIT();
        }

        // ---- accumulate (packed): d-pair dp, rows 0..3, j-quarter jq
        {
            const float* kpb = Kcur + 2 * dp;
            const float* vpb = Vs + 2 * dp;
#pragma unroll 4
            for (int jj = 0; jj < 16; jj++) {
                const int j = jq * 16 + jj;
                const ull kv = *(const ull*)&kpb[j * KP];
                const ull vv = *(const ull*)&vpb[j * KP];
                const ulonglong2 pA = *(const ulonglong2*)&p8d[j * 8];     // {p0,p0},{p1,p1}
                const ulonglong2 pB = *(const ulonglong2*)&p8d[j * 8 + 4]; // {p2,p2},{p3,p3}
                af0 = FMA2(pA.x, RELU2(ADD2(q0p, kv)), af0);
                av0 = FMA2(pA.x, vv, av0);
                af1 = FMA2(pA.y, RELU2(ADD2(q1p, kv)), af1);
                av1 = FMA2(pA.y, vv, av1);
                af2 = FMA2(pB.x, RELU2(ADD2(q2p, kv)), af2);
                av2 = FMA2(pB.x, vv, av2);
                af3 = FMA2(pB.y, RELU2(ADD2(q3p, kv)), af3);
                av3 = FMA2(pB.y, vv, av3);
            }
        }
    }

    // ================= epilogue =================
    // reduce l_acc over the 8 je-lanes of each g-group within the warp
#pragma unroll
    for (int off = 1; off <= 4; off <<= 1)
        l_acc += __shfl_xor_sync(0xffffffffu, l_acc, off);
    if ((lane & 7) == 0) l_ws[warp * 4 + g] = l_acc;
    CP_WAIT0();                      // drain any outstanding group
    __syncthreads();                 // main-loop reads done

    // exchange: xch[a][jq][dp] (a: 0-3 af rows, 4-7 av rows), in Ks0 region
    ull* xch = (ull*)Ks0;            // 8*4*64 ull = 4096 ull = 8192 floats <= 8448
    xch[(0 * 4 + jq) * 64 + dp] = af0;
    xch[(1 * 4 + jq) * 64 + dp] = af1;
    xch[(2 * 4 + jq) * 64 + dp] = af2;
    xch[(3 * 4 + jq) * 64 + dp] = af3;
    xch[(4 * 4 + jq) * 64 + dp] = av0;
    xch[(5 * 4 + jq) * 64 + dp] = av1;
    xch[(6 * 4 + jq) * 64 + dp] = av2;
    xch[(7 * 4 + jq) * 64 + dp] = av3;
    if (tid < 4) {                   // final denominator per row
        float s = 0.f;
#pragma unroll
        for (int w = 0; w < 8; w++) s += l_ws[w * 4 + tid];
        l_s[tid] = s;
    }
    __syncthreads();

    // combine over jq, normalize, publish Rp (in Vs) and avs (in Qe)
    float* Rp  = Vs;                 // [128][4] normalized R, k-major packed
    float* avs = Qe;                 // [4][128] normalized AV
    if (tid < 128) {
        const int dd = tid, dpc = tid >> 1, hc = tid & 1;
        const float* xf = (const float*)xch;
        const float4 l4 = *(const float4*)l_s;
        const float il[4] = {1.f / l4.x, 1.f / l4.y, 1.f / l4.z, 1.f / l4.w};
        float rp4[4];
#pragma unroll
        for (int r = 0; r < 4; r++) {
            float af = 0.f, av = 0.f;
#pragma unroll
            for (int q = 0; q < 4; q++) {
                af += xf[(((r    ) * 4 + q) * 64 + dpc) * 2 + hc];
                av += xf[(((4 + r) * 4 + q) * 64 + dpc) * 2 + hc];
            }
            rp4[r] = af * il[r];
            avs[r * 128 + dd] = av * il[r];
        }
        *(float4*)&Rp[dd * 4] = make_float4(rp4[0], rp4[1], rp4[2], rp4[3]);
    }
    __syncthreads();

    // GEMM: o[r][d] partial over k-range of this half
    const int d    = tid & 127;
    const int half = tid >> 7;
    float o0 = 0.f, o1 = 0.f, o2 = 0.f, o3 = 0.f;
    {
        const float* Wp = W_Ev + half * 64 * DIM + d;
#pragma unroll 4
        for (int k = 0; k < 64; k++) {
            const float wv = Wp[k * DIM];
            const float4 r4 = *(const float4*)&Rp[(half * 64 + k) * 4];  // broadcast
            o0 += r4.x * wv; o1 += r4.y * wv; o2 += r4.z * wv; o3 += r4.w * wv;
        }
    }
    __syncthreads();
    float* xg = Ks0;                 // reuse as [4][128]
    if (half == 1) {
        xg[0 * 128 + d] = o0; xg[1 * 128 + d] = o1;
        xg[2 * 128 + d] = o2; xg[3 * 128 + d] = o3;
    }
    __syncthreads();
    if (half == 0) {
        const float bv = b_Ev[d];
        o0 += xg[0 * 128 + d] + avs[0 * 128 + d] + bv;
        o1 += xg[1 * 128 + d] + avs[1 * 128 + d] + bv;
        o2 += xg[2 * 128 + d] + avs[2 * 128 + d] + bv;
        o3 += xg[3 * 128 + d] + avs[3 * 128 + d] + bv;
        out[(i0 + 0) * DIM + d] = o0;
        out[(i0 + 1) * DIM + d] = o1;
        out[(i0 + 2) * DIM + d] = o2;
        out[(i0 + 3) * DIM + d] = o3;
    }
}

// ---------------------------------------------------------------------------
extern "C" void kernel_launch(void* const* d_in, const int* in_sizes, int n_in,
                              void* d_out, int out_size)
{
    const float* x    = (const float*)d_in[0];
    const float* W_Q  = (const float*)d_in[1];
    const float* b_Q  = (const float*)d_in[2];
    const float* W_K  = (const float*)d_in[3];
    const float* b_K  = (const float*)d_in[4];
    const float* W_V  = (const float*)d_in[5];
    const float* b_V  = (const float*)d_in[6];
    const float* W_Ev = (const float*)d_in[7];
    const float* b_Ev = (const float*)d_in[8];
    const float* W_A  = (const float*)d_in[9];
    // d_in[10] = b_A: cancels in softmax; sum(alpha)=1 handles b_Ev; unused.
    float* out = (float*)d_out;

    const int smem2 = 26532 * (int)sizeof(float);  // 106128 B -> 2 CTAs/SM
    cudaFuncSetAttribute(attn_kernel, cudaFuncAttributeMaxDynamicSharedMemorySize, smem2);

    qkv_kernel<<<NTOK / 8, 384>>>(x, W_Q, b_Q, W_K, b_K, W_V, b_V);
    attn_kernel<<<NTOK / TI, NT, smem2>>>(W_A, W_Ev, b_Ev, out);
}

// round 13
// speedup vs baseline: 1.0828x; 1.0368x over previous
#include <cuda_runtime.h>
#include <math_constants.h>

#define NTOK 1024
#define DIM 128
#define TI 8            // rows per block (attn)
#define TJ 64           // j-tile
#define NT 512          // threads, attn
#define KP 132          // K/V smem pitch
#define NTILE (NTOK / TJ)
#define LOG2E 1.4426950408889634f

typedef unsigned long long ull;

// packed f32x2 helpers (sm_100+/sm_103a)
__device__ __forceinline__ ull ADD2(ull a, ull b) {
    ull r; asm("add.rn.f32x2 %0, %1, %2;" : "=l"(r) : "l"(a), "l"(b)); return r;
}
__device__ __forceinline__ ull FMA2(ull a, ull b, ull c) {
    ull r; asm("fma.rn.f32x2 %0, %1, %2, %3;" : "=l"(r) : "l"(a), "l"(b), "l"(c)); return r;
}
// packed relu via scalar FMNMX pair (no packed f32 max exists; FMNMX = alu pipe)
__device__ __forceinline__ ull RELU2(ull a) {
    float lo, hi;
    asm("mov.b64 {%0, %1}, %2;" : "=f"(lo), "=f"(hi) : "l"(a));
    lo = fmaxf(lo, 0.f); hi = fmaxf(hi, 0.f);
    ull r; asm("mov.b64 %0, {%1, %2};" : "=l"(r) : "f"(lo), "f"(hi)); return r;
}
__device__ __forceinline__ float HSUM2(ull a) {
    float lo, hi;
    asm("mov.b64 {%0, %1}, %2;" : "=f"(lo), "=f"(hi) : "l"(a));
    return lo + hi;
}
// cp.async 16B, L2-bypass-L1 variant
__device__ __forceinline__ void cpa16(unsigned dst, const void* src) {
    asm volatile("cp.async.cg.shared.global [%0], [%1], 16;" :: "r"(dst), "l"(src));
}
#define CP_COMMIT() asm volatile("cp.async.commit_group;" ::: "memory")
#define CP_WAIT0()  asm volatile("cp.async.wait_group 0;" ::: "memory")

// scratch for Q,K,V (static device arrays — no allocation)
__device__ float g_Q[NTOK * DIM];
__device__ float g_K[NTOK * DIM];
__device__ float g_V[NTOK * DIM];

// ---------------------------------------------------------------------------
// Kernel 1: Q,K,V = x @ W + b.  128 blocks x 384 threads.
// ---------------------------------------------------------------------------
__global__ __launch_bounds__(384) void qkv_kernel(
    const float* __restrict__ x,
    const float* __restrict__ WQ, const float* __restrict__ bQ,
    const float* __restrict__ WK, const float* __restrict__ bK,
    const float* __restrict__ WV, const float* __restrict__ bV)
{
    __shared__ float xs[8 * DIM];
    const int tid = threadIdx.x;
    const int i0 = blockIdx.x * 8;

    for (int idx = tid; idx < 8 * DIM; idx += 384)
        xs[idx] = x[i0 * DIM + idx];
    __syncthreads();

    const int d   = tid & 127;
    const int mat = tid >> 7;   // 0=Q 1=K 2=V
    const float* W = (mat == 0) ? WQ : (mat == 1) ? WK : WV;
    const float* b = (mat == 0) ? bQ : (mat == 1) ? bK : bV;
    float* outp    = (mat == 0) ? g_Q : (mat == 1) ? g_K : g_V;

    float acc[8];
    const float bv = b[d];
#pragma unroll
    for (int r = 0; r < 8; r++) acc[r] = bv;

#pragma unroll 4
    for (int k = 0; k < DIM; k += 4) {
        const float w0 = W[(k + 0) * DIM + d];
        const float w1 = W[(k + 1) * DIM + d];
        const float w2 = W[(k + 2) * DIM + d];
        const float w3 = W[(k + 3) * DIM + d];
#pragma unroll
        for (int r = 0; r < 8; r++) {
            const float4 xq = *(const float4*)&xs[r * DIM + k];
            acc[r] = fmaf(xq.x, w0, fmaf(xq.y, w1, fmaf(xq.z, w2, fmaf(xq.w, w3, acc[r]))));
        }
    }
#pragma unroll
    for (int r = 0; r < 8; r++)
        outp[(i0 + r) * DIM + d] = acc[r];
}

// ---------------------------------------------------------------------------
// Kernel 2: fused pass, TI=8, ONE 512-thread CTA per SM (grid 128, 1 wave).
//   K and V both double-buffered via cp.async; per tile: 1 wait + 2 barriers.
//   phase-e: warp w: row-half rh_e=w>>3, je=(w&7)*8+(lane&7), g=lane>>3;
//            3-shfl reduce-scatter -> thread owns row rh_e*4+g at column je;
//            1 exp2/thread; p stored duplicated to p16d[j][16].
//   accumulate: thread (dp=tid&63, jq=(tid>>6)&3, rh=tid>>8): rows rh*4..+3,
//            16 j; packed f32x2 accumulators; K/V L2 traffic once per SM.
// smem ~144KB -> 1 CTA/SM (by design).
// ---------------------------------------------------------------------------
__global__ __launch_bounds__(NT, 1) void attn_kernel(
    const float* __restrict__ wA,
    const float* __restrict__ W_Ev,
    const float* __restrict__ b_Ev,
    float* __restrict__ out)
{
    extern __shared__ float sm[];
    float* Ks0  = sm;              // [TJ][KP] = 8448
    float* Ks1  = sm + 8448;
    float* Vs0  = sm + 16896;
    float* Vs1  = sm + 25344;
    float* Qe   = sm + 33792;      // [8][DIM] = 1024
    float* wAs  = sm + 34816;      // [DIM] = 128
    float* p16d = sm + 34944;      // [TJ][16] duplicated p = 1024
    float* l_ws = sm + 35968;      // [16][4] = 64
    // total 36032 floats = 144128 B

    const int tid  = threadIdx.x;
    const int lane = tid & 31;
    const int warp = tid >> 5;
    const int i0   = blockIdx.x * TI;
    // phase-e ids
    const int rh_e = warp >> 3;               // row half 0/1
    const int je   = (warp & 7) * 8 + (lane & 7);
    const int g    = lane >> 3;               // d-chunk / owned local row
    // accumulate ids
    const int dp   = tid & 63;                // d-pair
    const int jq   = (tid >> 6) & 3;          // j-quarter
    const int rh   = tid >> 8;                // row half 0/1

    // per-thread tile slots: float4 idx = it*NT + tid (4 slots)
    unsigned koff[4], kb0, kb1, vb0, vb1;
    {
        kb0 = (unsigned)__cvta_generic_to_shared(Ks0);
        kb1 = (unsigned)__cvta_generic_to_shared(Ks1);
        vb0 = (unsigned)__cvta_generic_to_shared(Vs0);
        vb1 = (unsigned)__cvta_generic_to_shared(Vs1);
#pragma unroll
        for (int it = 0; it < 4; it++) {
            const int idx = it * NT + tid;
            koff[it] = (unsigned)(((idx >> 5) * KP + (idx & 31) * 4) * 4);
        }
    }

    // init Q table (row-major, 8 rows) + wA
    for (int idx = tid; idx < TI * DIM; idx += NT) {
        const int r = idx >> 7, dd = idx & 127;
        Qe[idx] = g_Q[(i0 + r) * DIM + dd];
    }
    if (tid < DIM) wAs[tid] = wA[tid];

    // accumulate-phase Q d-pairs (rows rh*4..rh*4+3)
    const ull q0p = *(const ull*)&g_Q[(i0 + rh * 4 + 0) * DIM + 2 * dp];
    const ull q1p = *(const ull*)&g_Q[(i0 + rh * 4 + 1) * DIM + 2 * dp];
    const ull q2p = *(const ull*)&g_Q[(i0 + rh * 4 + 2) * DIM + 2 * dp];
    const ull q3p = *(const ull*)&g_Q[(i0 + rh * 4 + 3) * DIM + 2 * dp];

    ull af0 = 0ull, af1 = 0ull, af2 = 0ull, af3 = 0ull;
    ull av0 = 0ull, av1 = 0ull, av2 = 0ull, av3 = 0ull;
    float l_acc = 0.f;   // row rh_e*4+g, columns je (one per tile)

    // prologue: async-load K(0), V(0)
    {
        const float4* Kg = (const float4*)(g_K);
        const float4* Vg = (const float4*)(g_V);
#pragma unroll
        for (int it = 0; it < 4; it++) {
            cpa16(kb0 + koff[it], &Kg[it * NT + tid]);
            cpa16(vb0 + koff[it], &Vg[it * NT + tid]);
        }
        CP_COMMIT();
    }

    for (int ti = 0; ti < NTILE; ti++) {
        const float* Kcur = (ti & 1) ? Ks1 : Ks0;
        const float* Vcur = (ti & 1) ? Vs1 : Vs0;

        CP_WAIT0();        // K(ti), V(ti) landed
        __syncthreads();   // visible; prev accumulate done (covers Qe/wAs ti=0)

        // ---- phase e/p: e over d-chunk g for 4 rows (half rh_e) at column je
        {
            ull e0 = 0ull, e1 = 0ull, e2 = 0ull, e3 = 0ull;
            const float* kp = Kcur + je * KP;
            const float* Qh = Qe + rh_e * 4 * DIM;
#pragma unroll
            for (int it = 0; it < 8; it++) {
                const int b = (g + it * 4) * 4;
                const ulonglong2 k2 = *(const ulonglong2*)&kp[b];
                const ulonglong2 w2 = *(const ulonglong2*)&wAs[b];
                {
                    const ulonglong2 q2 = *(const ulonglong2*)&Qh[0 * DIM + b];
                    e0 = FMA2(RELU2(ADD2(q2.x, k2.x)), w2.x, e0);
                    e0 = FMA2(RELU2(ADD2(q2.y, k2.y)), w2.y, e0);
                }
                {
                    const ulonglong2 q2 = *(const ulonglong2*)&Qh[1 * DIM + b];
                    e1 = FMA2(RELU2(ADD2(q2.x, k2.x)), w2.x, e1);
                    e1 = FMA2(RELU2(ADD2(q2.y, k2.y)), w2.y, e1);
                }
                {
                    const ulonglong2 q2 = *(const ulonglong2*)&Qh[2 * DIM + b];
                    e2 = FMA2(RELU2(ADD2(q2.x, k2.x)), w2.x, e2);
                    e2 = FMA2(RELU2(ADD2(q2.y, k2.y)), w2.y, e2);
                }
                {
                    const ulonglong2 q2 = *(const ulonglong2*)&Qh[3 * DIM + b];
                    e3 = FMA2(RELU2(ADD2(q2.x, k2.x)), w2.x, e3);
                    e3 = FMA2(RELU2(ADD2(q2.y, k2.y)), w2.y, e3);
                }
            }
            float f0 = HSUM2(e0), f1 = HSUM2(e1), f2 = HSUM2(e2), f3 = HSUM2(e3);
            // reduce-scatter over g (3 shfls): thread owns local row g
            const bool hi0 = (g & 1);
            float sA = hi0 ? f0 : f1;
            float sB = hi0 ? f2 : f3;
            const float rA = __shfl_xor_sync(0xffffffffu, sA, 8);
            const float rB = __shfl_xor_sync(0xffffffffu, sB, 8);
            const float u = (hi0 ? f1 : f0) + rA;
            const float v = (hi0 ? f3 : f2) + rB;
            const bool hi1 = (g >> 1);
            float s2 = hi1 ? u : v;
            const float r2 = __shfl_xor_sync(0xffffffffu, s2, 16);
            const float e = (hi1 ? v : u) + r2;     // row rh_e*4+g, col je
            const float p = exp2f(e * LOG2E);       // |e| <~ 3: no max-shift
            *(float2*)&p16d[je * 16 + 2 * (rh_e * 4 + g)] = make_float2(p, p);
            l_acc += p;
        }
        __syncthreads();   // p16d ready; phase-e reads of Kcur done

        // issue K(ti+1), V(ti+1) into other buffers — overlaps accumulate
        if (ti + 1 < NTILE) {
            const unsigned kbn = (ti & 1) ? kb0 : kb1;
            const unsigned vbn = (ti & 1) ? vb0 : vb1;
            const float4* Kg = (const float4*)(g_K + (ti + 1) * TJ * DIM);
            const float4* Vg = (const float4*)(g_V + (ti + 1) * TJ * DIM);
#pragma unroll
            for (int it = 0; it < 4; it++) {
                cpa16(kbn + koff[it], &Kg[it * NT + tid]);
                cpa16(vbn + koff[it], &Vg[it * NT + tid]);
            }
            CP_COMMIT();
        }

        // ---- accumulate: d-pair dp, rows rh*4..+3, j-quarter jq
        {
            const float* kpb = Kcur + 2 * dp;
            const float* vpb = Vcur + 2 * dp;
            const float* pp  = p16d + 8 * rh;
#pragma unroll 4
            for (int jj = 0; jj < 16; jj++) {
                const int j = jq * 16 + jj;
                const ull kv = *(const ull*)&kpb[j * KP];
                const ull vv = *(const ull*)&vpb[j * KP];
                const ulonglong2 pA = *(const ulonglong2*)&pp[j * 16];     // rows 4rh,4rh+1
                const ulonglong2 pB = *(const ulonglong2*)&pp[j * 16 + 4]; // rows 4rh+2,4rh+3
                af0 = FMA2(pA.x, RELU2(ADD2(q0p, kv)), af0);
                av0 = FMA2(pA.x, vv, av0);
                af1 = FMA2(pA.y, RELU2(ADD2(q1p, kv)), af1);
                av1 = FMA2(pA.y, vv, av1);
                af2 = FMA2(pB.x, RELU2(ADD2(q2p, kv)), af2);
                av2 = FMA2(pB.x, vv, av2);
                af3 = FMA2(pB.y, RELU2(ADD2(q3p, kv)), af3);
                av3 = FMA2(pB.y, vv, av3);
            }
        }
    }

    // ================= epilogue =================
    // reduce l_acc over the 8 je-lanes of each g-group
#pragma unroll
    for (int off = 1; off <= 4; off <<= 1)
        l_acc += __shfl_xor_sync(0xffffffffu, l_acc, off);
    if ((lane & 7) == 0) l_ws[warp * 4 + g] = l_acc;

    // exchange: xch[rh][acc 0..7][jq][dp] as ull, in Ks0 region (32KB <= 33KB)
    ull* xch = (ull*)Ks0;
    {
        const int bse = ((rh * 8 + 0) * 4 + jq) * 64 + dp;
        xch[bse + 0 * 256] = af0;   // acc a at offset ((rh*8+a)*4+jq)*64+dp
        xch[bse + 1 * 256] = af1;
        xch[bse + 2 * 256] = af2;
        xch[bse + 3 * 256] = af3;
        xch[bse + 4 * 256] = av0;
        xch[bse + 5 * 256] = av1;
        xch[bse + 6 * 256] = av2;
        xch[bse + 7 * 256] = av3;
    }
    __syncthreads();

    // combine over jq, normalize; Rp[k][8] in Vs0, avs[8][128] in Qe
    float* Rp  = Vs0;
    float* avs = Qe;
    {
        const int d = tid & 127, rp = tid >> 7;      // rows 2rp, 2rp+1
        const int dpc = d >> 1, hc = d & 1;
        const float* xf = (const float*)xch;
#pragma unroll
        for (int rr = 0; rr < 2; rr++) {
            const int r = 2 * rp + rr;
            const int rhh = r >> 2, ra = r & 3;
            // denominator for row r
            float lr = 0.f;
#pragma unroll
            for (int w = 0; w < 8; w++) lr += l_ws[(rhh * 8 + w) * 4 + ra];
            const float il = 1.f / lr;
            float af = 0.f, av = 0.f;
#pragma unroll
            for (int q = 0; q < 4; q++) {
                af += xf[(((rhh * 8 + ra    ) * 4 + q) * 64 + dpc) * 2 + hc];
                av += xf[(((rhh * 8 + 4 + ra) * 4 + q) * 64 + dpc) * 2 + hc];
            }
            Rp[d * 8 + r]       = af * il;
            avs[r * 128 + d]    = av * il;
        }
    }
    __syncthreads();

    // GEMM: thread (d, s=tid>>7) computes rows 2s, 2s+1 over full k
    {
        const int d = tid & 127, s = tid >> 7;
        const float bv = b_Ev[d];
        float o0 = avs[(2 * s) * 128 + d] + bv;
        float o1 = avs[(2 * s + 1) * 128 + d] + bv;
#pragma unroll 4
        for (int k = 0; k < DIM; k++) {
            const float wv = W_Ev[k * DIM + d];
            const float2 r2 = *(const float2*)&Rp[k * 8 + 2 * s];  // broadcast
            o0 += r2.x * wv;
            o1 += r2.y * wv;
        }
        out[(i0 + 2 * s) * DIM + d]     = o0;
        out[(i0 + 2 * s + 1) * DIM + d] = o1;
    }
}

// ---------------------------------------------------------------------------
extern "C" void kernel_launch(void* const* d_in, const int* in_sizes, int n_in,
                              void* d_out, int out_size)
{
    const float* x    = (const float*)d_in[0];
    const float* W_Q  = (const float*)d_in[1];
    const float* b_Q  = (const float*)d_in[2];
    const float* W_K  = (const float*)d_in[3];
    const float* b_K  = (const float*)d_in[4];
    const float* W_V  = (const float*)d_in[5];
    const float* b_V  = (const float*)d_in[6];
    const float* W_Ev = (const float*)d_in[7];
    const float* b_Ev = (const float*)d_in[8];
    const float* W_A  = (const float*)d_in[9];
    // d_in[10] = b_A: cancels in softmax; sum(alpha)=1 handles b_Ev; unused.
    float* out = (float*)d_out;

    const int smem2 = 36032 * (int)sizeof(float);  // 144128 B -> 1 CTA/SM
    cudaFuncSetAttribute(attn_kernel, cudaFuncAttributeMaxDynamicSharedMemorySize, smem2);

    qkv_kernel<<<NTOK / 8, 384>>>(x, W_Q, b_Q, W_K, b_K, W_V, b_V);
    attn_kernel<<<NTOK / TI, NT, smem2>>>(W_A, W_Ev, b_Ev, out);
}

// round 14
// speedup vs baseline: 1.1360x; 1.0491x over previous
#include <cuda_runtime.h>
#include <math_constants.h>

#define NTOK 1024
#define DIM 128
#define TI 8            // rows per block (attn)
#define TJ 64           // j-tile
#define NT 512          // threads, attn
#define KP 132          // K/V smem pitch
#define NTILE (NTOK / TJ)
#define LOG2E 1.4426950408889634f

typedef unsigned long long ull;

// packed f32x2 helpers (sm_100+/sm_103a)
__device__ __forceinline__ ull ADD2(ull a, ull b) {
    ull r; asm("add.rn.f32x2 %0, %1, %2;" : "=l"(r) : "l"(a), "l"(b)); return r;
}
__device__ __forceinline__ ull FMA2(ull a, ull b, ull c) {
    ull r; asm("fma.rn.f32x2 %0, %1, %2, %3;" : "=l"(r) : "l"(a), "l"(b), "l"(c)); return r;
}
// packed relu via scalar FMNMX pair (no packed f32 max; FMNMX = alu pipe)
__device__ __forceinline__ ull RELU2(ull a) {
    float lo, hi;
    asm("mov.b64 {%0, %1}, %2;" : "=f"(lo), "=f"(hi) : "l"(a));
    lo = fmaxf(lo, 0.f); hi = fmaxf(hi, 0.f);
    ull r; asm("mov.b64 %0, {%1, %2};" : "=l"(r) : "f"(lo), "f"(hi)); return r;
}
__device__ __forceinline__ float HSUM2(ull a) {
    float lo, hi;
    asm("mov.b64 {%0, %1}, %2;" : "=f"(lo), "=f"(hi) : "l"(a));
    return lo + hi;
}
// cp.async 16B
__device__ __forceinline__ void cpa16(unsigned dst, const void* src) {
    asm volatile("cp.async.cg.shared.global [%0], [%1], 16;" :: "r"(dst), "l"(src));
}
#define CP_COMMIT() asm volatile("cp.async.commit_group;" ::: "memory")
#define CP_WAIT0()  asm volatile("cp.async.wait_group 0;" ::: "memory")

// scratch for Q,K,V (static device arrays — no allocation)
__device__ float g_Q[NTOK * DIM];
__device__ float g_K[NTOK * DIM];
__device__ float g_V[NTOK * DIM];

// ---------------------------------------------------------------------------
// Kernel 1: Q,K,V = x @ W + b.  128 blocks x 384 threads.
// ---------------------------------------------------------------------------
__global__ __launch_bounds__(384) void qkv_kernel(
    const float* __restrict__ x,
    const float* __restrict__ WQ, const float* __restrict__ bQ,
    const float* __restrict__ WK, const float* __restrict__ bK,
    const float* __restrict__ WV, const float* __restrict__ bV)
{
    __shared__ float xs[8 * DIM];
    const int tid = threadIdx.x;
    const int i0 = blockIdx.x * 8;

    for (int idx = tid; idx < 8 * DIM; idx += 384)
        xs[idx] = x[i0 * DIM + idx];
    __syncthreads();

    const int d   = tid & 127;
    const int mat = tid >> 7;   // 0=Q 1=K 2=V
    const float* W = (mat == 0) ? WQ : (mat == 1) ? WK : WV;
    const float* b = (mat == 0) ? bQ : (mat == 1) ? bK : bV;
    float* outp    = (mat == 0) ? g_Q : (mat == 1) ? g_K : g_V;

    float acc[8];
    const float bv = b[d];
#pragma unroll
    for (int r = 0; r < 8; r++) acc[r] = bv;

#pragma unroll 4
    for (int k = 0; k < DIM; k += 4) {
        const float w0 = W[(k + 0) * DIM + d];
        const float w1 = W[(k + 1) * DIM + d];
        const float w2 = W[(k + 2) * DIM + d];
        const float w3 = W[(k + 3) * DIM + d];
#pragma unroll
        for (int r = 0; r < 8; r++) {
            const float4 xq = *(const float4*)&xs[r * DIM + k];
            acc[r] = fmaf(xq.x, w0, fmaf(xq.y, w1, fmaf(xq.z, w2, fmaf(xq.w, w3, acc[r]))));
        }
    }
#pragma unroll
    for (int r = 0; r < 8; r++)
        outp[(i0 + r) * DIM + d] = acc[r];
}

// ---- phase bodies as macros (straight-line, interleavable) -----------------
#define E_IT(it) { \
    const int b_ = (g + (it) * 4) * 4; \
    const ulonglong2 k2 = *(const ulonglong2*)&kpE[b_]; \
    const ulonglong2 w2 = *(const ulonglong2*)&wAs[b_]; \
    { const ulonglong2 q2 = *(const ulonglong2*)&QhE[0 * DIM + b_]; \
      e0 = FMA2(RELU2(ADD2(q2.x, k2.x)), w2.x, e0); \
      e0 = FMA2(RELU2(ADD2(q2.y, k2.y)), w2.y, e0); } \
    { const ulonglong2 q2 = *(const ulonglong2*)&QhE[1 * DIM + b_]; \
      e1 = FMA2(RELU2(ADD2(q2.x, k2.x)), w2.x, e1); \
      e1 = FMA2(RELU2(ADD2(q2.y, k2.y)), w2.y, e1); } \
    { const ulonglong2 q2 = *(const ulonglong2*)&QhE[2 * DIM + b_]; \
      e2 = FMA2(RELU2(ADD2(q2.x, k2.x)), w2.x, e2); \
      e2 = FMA2(RELU2(ADD2(q2.y, k2.y)), w2.y, e2); } \
    { const ulonglong2 q2 = *(const ulonglong2*)&QhE[3 * DIM + b_]; \
      e3 = FMA2(RELU2(ADD2(q2.x, k2.x)), w2.x, e3); \
      e3 = FMA2(RELU2(ADD2(q2.y, k2.y)), w2.y, e3); } }

#define E_FIN() { \
    float f0 = HSUM2(e0), f1 = HSUM2(e1), f2 = HSUM2(e2), f3 = HSUM2(e3); \
    const bool hi0 = (g & 1); \
    float sA = hi0 ? f0 : f1; \
    float sB = hi0 ? f2 : f3; \
    const float rA = __shfl_xor_sync(0xffffffffu, sA, 8); \
    const float rB = __shfl_xor_sync(0xffffffffu, sB, 8); \
    const float u_ = (hi0 ? f1 : f0) + rA; \
    const float v_ = (hi0 ? f3 : f2) + rB; \
    const bool hi1 = (g >> 1); \
    float s2 = hi1 ? u_ : v_; \
    const float r2 = __shfl_xor_sync(0xffffffffu, s2, 16); \
    const float e_ = (hi1 ? v_ : u_) + r2; \
    const float p_ = exp2f(e_ * LOG2E); \
    *(float2*)&p_cur[je * 16 + 2 * (rh_e * 4 + g)] = make_float2(p_, p_); \
    l_acc += p_; }

#define ACC_J(jj) { \
    const int j_ = jq * 16 + (jj); \
    const ull kv = *(const ull*)&kpA[j_ * KP]; \
    const ull vv = *(const ull*)&vpA[j_ * KP]; \
    const ulonglong2 pA = *(const ulonglong2*)&ppA[j_ * 16]; \
    const ulonglong2 pB = *(const ulonglong2*)&ppA[j_ * 16 + 4]; \
    af0 = FMA2(pA.x, RELU2(ADD2(q0p, kv)), af0); av0 = FMA2(pA.x, vv, av0); \
    af1 = FMA2(pA.y, RELU2(ADD2(q1p, kv)), af1); av1 = FMA2(pA.y, vv, av1); \
    af2 = FMA2(pB.x, RELU2(ADD2(q2p, kv)), af2); av2 = FMA2(pB.x, vv, av2); \
    af3 = FMA2(pB.y, RELU2(ADD2(q3p, kv)), af3); av3 = FMA2(pB.y, vv, av3); }

// ---------------------------------------------------------------------------
// Kernel 2: fused pass, TI=8, 1 CTA/SM, intra-thread software pipeline:
//   merged phase per tile ti: phase-e(ti) + accumulate(ti-1) interleaved in
//   straight-line code; K,V triple-buffered, p double-buffered.
//   ONE __syncthreads per tile; cp.async(ti+1) overlaps the merged phase.
// smem 215.8 KB.
// ---------------------------------------------------------------------------
__global__ __launch_bounds__(NT, 1) void attn_kernel(
    const float* __restrict__ wA,
    const float* __restrict__ W_Ev,
    const float* __restrict__ b_Ev,
    float* __restrict__ out)
{
    extern __shared__ float sm[];
    float* Kb0  = sm;              // 3 x [TJ][KP] = 3 x 8448
    float* Kb1  = sm + 8448;
    float* Kb2  = sm + 16896;
    float* Vb0  = sm + 25344;
    float* Vb1  = sm + 33792;
    float* Vb2  = sm + 42240;
    float* Qe   = sm + 50688;      // [8][DIM] = 1024
    float* wAs  = sm + 51712;      // [DIM] = 128
    float* pb0  = sm + 51840;      // [TJ][16] = 1024
    float* pb1  = sm + 52864;      // 1024
    float* l_ws = sm + 53888;      // [16][4] = 64
    // total 53952 floats = 215808 B

    const int tid  = threadIdx.x;
    const int lane = tid & 31;
    const int warp = tid >> 5;
    const int i0   = blockIdx.x * TI;
    // phase-e ids
    const int rh_e = warp >> 3;               // row half 0/1
    const int je   = (warp & 7) * 8 + (lane & 7);
    const int g    = lane >> 3;               // d-chunk / owned local row
    // accumulate ids
    const int dp   = tid & 63;                // d-pair
    const int jq   = (tid >> 6) & 3;          // j-quarter
    const int rh   = tid >> 8;                // row half 0/1

    // per-thread tile slots: float4 idx = it*NT + tid (4 slots)
    unsigned koff[4];
#pragma unroll
    for (int it = 0; it < 4; it++) {
        const int idx = it * NT + tid;
        koff[it] = (unsigned)(((idx >> 5) * KP + (idx & 31) * 4) * 4);
    }

    // init Q table (row-major, 8 rows) + wA
    for (int idx = tid; idx < TI * DIM; idx += NT) {
        const int r = idx >> 7, dd = idx & 127;
        Qe[idx] = g_Q[(i0 + r) * DIM + dd];
    }
    if (tid < DIM) wAs[tid] = wA[tid];

    // accumulate-phase Q d-pairs (rows rh*4..rh*4+3)
    const ull q0p = *(const ull*)&g_Q[(i0 + rh * 4 + 0) * DIM + 2 * dp];
    const ull q1p = *(const ull*)&g_Q[(i0 + rh * 4 + 1) * DIM + 2 * dp];
    const ull q2p = *(const ull*)&g_Q[(i0 + rh * 4 + 2) * DIM + 2 * dp];
    const ull q3p = *(const ull*)&g_Q[(i0 + rh * 4 + 3) * DIM + 2 * dp];

    ull af0 = 0ull, af1 = 0ull, af2 = 0ull, af3 = 0ull;
    ull av0 = 0ull, av1 = 0ull, av2 = 0ull, av3 = 0ull;
    float l_acc = 0.f;

    // rotating buffers: at top of iter ti, Ke=K(ti), Ka=K(ti-1), Kn=load tgt
    float *Ke = Kb0, *Ka = Kb2, *Kn = Kb1;
    float *Vf = Vb0, *Va = Vb2, *Vn = Vb1;
    float *p_cur = pb0, *p_prev = pb1;

    // prologue: async-load K(0), V(0) into buf0
    {
        const unsigned ka = (unsigned)__cvta_generic_to_shared(Kb0);
        const unsigned va = (unsigned)__cvta_generic_to_shared(Vb0);
        const float4* Kg = (const float4*)(g_K);
        const float4* Vg = (const float4*)(g_V);
#pragma unroll
        for (int it = 0; it < 4; it++) {
            cpa16(ka + koff[it], &Kg[it * NT + tid]);
            cpa16(va + koff[it], &Vg[it * NT + tid]);
        }
        CP_COMMIT();
    }

    for (int ti = 0; ti < NTILE; ti++) {
        CP_WAIT0();        // K(ti), V(ti) landed
        __syncthreads();   // p(ti-1) visible; buffers safe to rotate/overwrite

        // issue K(ti+1), V(ti+1) — overlaps whole merged phase
        if (ti + 1 < NTILE) {
            const unsigned kna = (unsigned)__cvta_generic_to_shared(Kn);
            const unsigned vna = (unsigned)__cvta_generic_to_shared(Vn);
            const float4* Kg = (const float4*)(g_K + (ti + 1) * TJ * DIM);
            const float4* Vg = (const float4*)(g_V + (ti + 1) * TJ * DIM);
#pragma unroll
            for (int it = 0; it < 4; it++) {
                cpa16(kna + koff[it], &Kg[it * NT + tid]);
                cpa16(vna + koff[it], &Vg[it * NT + tid]);
            }
            CP_COMMIT();
        }

        if (ti == 0) {
            // e-only
            ull e0 = 0ull, e1 = 0ull, e2 = 0ull, e3 = 0ull;
            const float* kpE = Ke + je * KP;
            const float* QhE = Qe + rh_e * 4 * DIM;
#pragma unroll
            for (int it = 0; it < 8; it++) E_IT(it);
            E_FIN();
        } else {
            // merged: phase-e(ti) + accumulate(ti-1), interleaved
            ull e0 = 0ull, e1 = 0ull, e2 = 0ull, e3 = 0ull;
            const float* kpE = Ke + je * KP;
            const float* QhE = Qe + rh_e * 4 * DIM;
            const float* kpA = Ka + 2 * dp;
            const float* vpA = Va + 2 * dp;
            const float* ppA = p_prev + 8 * rh;
#pragma unroll
            for (int u = 0; u < 16; u++) {
                ACC_J(u);
                if ((u & 1) == 0) E_IT(u >> 1);
            }
            E_FIN();
        }

        // rotate buffers
        float* t;
        t = Ka; Ka = Ke; Ke = Kn; Kn = t;
        t = Va; Va = Vf; Vf = Vn; Vn = t;
        t = p_prev; p_prev = p_cur; p_cur = t;
    }

    __syncthreads();       // p(15) visible
    {   // final accumulate(15): Ka=K(15), Va=V(15), p_prev=p(15)
        const float* kpA = Ka + 2 * dp;
        const float* vpA = Va + 2 * dp;
        const float* ppA = p_prev + 8 * rh;
#pragma unroll 4
        for (int u = 0; u < 16; u++) ACC_J(u);
    }

    // ================= epilogue =================
    // reduce l_acc over the 8 je-lanes of each g-group
#pragma unroll
    for (int off = 1; off <= 4; off <<= 1)
        l_acc += __shfl_xor_sync(0xffffffffu, l_acc, off);
    if ((lane & 7) == 0) l_ws[warp * 4 + g] = l_acc;

    // exchange in Kb1 (final acc used buf0): xch[rh][acc 0..7][jq][dp]
    ull* xch = (ull*)Kb1;
    {
        const int bse = ((rh * 8 + 0) * 4 + jq) * 64 + dp;
        xch[bse + 0 * 256] = af0;
        xch[bse + 1 * 256] = af1;
        xch[bse + 2 * 256] = af2;
        xch[bse + 3 * 256] = af3;
        xch[bse + 4 * 256] = av0;
        xch[bse + 5 * 256] = av1;
        xch[bse + 6 * 256] = av2;
        xch[bse + 7 * 256] = av3;
    }
    __syncthreads();

    // combine over jq, normalize; Rp[k][8] in Vb1, avs[8][128] in Qe
    float* Rp  = Vb1;
    float* avs = Qe;
    {
        const int d = tid & 127, rp = tid >> 7;      // rows 2rp, 2rp+1
        const int dpc = d >> 1, hc = d & 1;
        const float* xf = (const float*)xch;
#pragma unroll
        for (int rr = 0; rr < 2; rr++) {
            const int r = 2 * rp + rr;
            const int rhh = r >> 2, ra = r & 3;
            float lr = 0.f;
#pragma unroll
            for (int w = 0; w < 8; w++) lr += l_ws[(rhh * 8 + w) * 4 + ra];
            const float il = 1.f / lr;
            float af = 0.f, av = 0.f;
#pragma unroll
            for (int q = 0; q < 4; q++) {
                af += xf[(((rhh * 8 + ra    ) * 4 + q) * 64 + dpc) * 2 + hc];
                av += xf[(((rhh * 8 + 4 + ra) * 4 + q) * 64 + dpc) * 2 + hc];
            }
            Rp[d * 8 + r]    = af * il;
            avs[r * 128 + d] = av * il;
        }
    }
    __syncthreads();

    // GEMM: thread (d, s=tid>>7) computes rows 2s, 2s+1 over full k
    {
        const int d = tid & 127, s = tid >> 7;
        const float bv = b_Ev[d];
        float o0 = avs[(2 * s) * 128 + d] + bv;
        float o1 = avs[(2 * s + 1) * 128 + d] + bv;
#pragma unroll 4
        for (int k = 0; k < DIM; k++) {
            const float wv = W_Ev[k * DIM + d];
            const float2 r2 = *(const float2*)&Rp[k * 8 + 2 * s];  // broadcast
            o0 += r2.x * wv;
            o1 += r2.y * wv;
        }
        out[(i0 + 2 * s) * DIM + d]     = o0;
        out[(i0 + 2 * s + 1) * DIM + d] = o1;
    }
}

// ---------------------------------------------------------------------------
extern "C" void kernel_launch(void* const* d_in, const int* in_sizes, int n_in,
                              void* d_out, int out_size)
{
    const float* x    = (const float*)d_in[0];
    const float* W_Q  = (const float*)d_in[1];
    const float* b_Q  = (const float*)d_in[2];
    const float* W_K  = (const float*)d_in[3];
    const float* b_K  = (const float*)d_in[4];
    const float* W_V  = (const float*)d_in[5];
    const float* b_V  = (const float*)d_in[6];
    const float* W_Ev = (const float*)d_in[7];
    const float* b_Ev = (const float*)d_in[8];
    const float* W_A  = (const float*)d_in[9];
    // d_in[10] = b_A: cancels in softmax; sum(alpha)=1 handles b_Ev; unused.
    float* out = (float*)d_out;

    const int smem2 = 53952 * (int)sizeof(float);  // 215808 B -> 1 CTA/SM
    cudaFuncSetAttribute(attn_kernel, cudaFuncAttributeMaxDynamicSharedMemorySize, smem2);

    qkv_kernel<<<NTOK / 8, 384>>>(x, W_Q, b_Q, W_K, b_K, W_V, b_V);
    attn_kernel<<<NTOK / TI, NT, smem2>>>(W_A, W_Ev, b_Ev, out);
}